// round 11
// baseline (speedup 1.0000x reference)
#include <cuda_runtime.h>
#include <cuda_bf16.h>
#include <cstdint>

// ---------------- problem constants ----------------
#define B_    32
#define T_    300
#define FIN   3072
#define FH    410
#define FHP   448                  // FH padded to BN multiple
#define FOUT  10
#define NTOT  (B_*T_*FIN)          // 29,491,200
#define MTOT  (B_*T_)              // 9600 = 75 * 128
#define THETA 10.0f
#define DECAY 0.9048374166859746f  // exp(f32(-0.1))

// ---------------- GEMM1 tiling ----------------
#define BM 128
#define BN 64
#define BK 64                      // bf16 per k-stage -> 128B rows
#define KBLKS (FIN/BK)             // 48
#define NSTAGE 3
#define STAGE_A (BM*128)           // 16384
#define STAGE_B (2*BN*128)         // 16384 (hi+mid splits)
#define STAGE_BYTES (STAGE_A + STAGE_B)        // 32768
#define GEMM1_SMEM  (NSTAGE*STAGE_BYTES)       // 98304

// ---------------- scratch ----------------
__device__ __align__(16) __nv_bfloat16 g_spkb[(size_t)MTOT*FIN];  // spikes bf16
__device__ __align__(16) __nv_bfloat16 g_w1b[2u*FHP*FIN];         // hi/mid splits
__device__ float   g_a1T[(size_t)FH*MTOT];     // a1 transposed [n][m]
__device__ __align__(4) uint8_t g_s1T[(size_t)B_*FH*T_];  // layer-1 spikes [b][o][t]
__device__ float   g_a2[(size_t)MTOT*FOUT];    // [b*t][i]

// ---------------- PTX helpers (all >= compute_80) ----------------
__device__ __forceinline__ uint32_t s2u(const void* p) {
    uint32_t a;
    asm("{ .reg .u64 t; cvta.to.shared.u64 t, %1; cvt.u32.u64 %0, t; }"
        : "=r"(a) : "l"(p));
    return a;
}
__device__ __forceinline__ void cp16(uint32_t dst, const void* src) {
    asm volatile("cp.async.cg.shared.global [%0], [%1], 16;"
                 :: "r"(dst), "l"(src));
}
#define CP_COMMIT() asm volatile("cp.async.commit_group;" ::: "memory")
#define CP_WAIT(n)  asm volatile("cp.async.wait_group %0;" :: "n"(n) : "memory")

#define LDSM4(r, addr) \
    asm volatile("ldmatrix.sync.aligned.m8n8.x4.shared.b16 {%0,%1,%2,%3}, [%4];" \
        : "=r"((r)[0]), "=r"((r)[1]), "=r"((r)[2]), "=r"((r)[3]) : "r"(addr))

#define MMA16816(d, a, b0, b1) \
    asm volatile("mma.sync.aligned.m16n8k16.row.col.f32.bf16.bf16.f32 " \
        "{%0,%1,%2,%3}, {%4,%5,%6,%7}, {%8,%9}, {%0,%1,%2,%3};" \
        : "+f"((d)[0]), "+f"((d)[1]), "+f"((d)[2]), "+f"((d)[3]) \
        : "r"((a)[0]), "r"((a)[1]), "r"((a)[2]), "r"((a)[3]), "r"(b0), "r"(b1))

__device__ __forceinline__ uint32_t sw128(uint32_t off) {
    return off ^ ((off >> 3) & 0x70u);
}

// ---------------- threefry-2x32 (JAX partitionable mode, verified exact) ---
__device__ __forceinline__ uint2 threefry2x32(uint32_t k0, uint32_t k1,
                                              uint32_t x0, uint32_t x1) {
    uint32_t ks2 = k0 ^ k1 ^ 0x1BD11BDAu;
    x0 += k0; x1 += k1;
#define TF_R(r) { x0 += x1; x1 = __funnelshift_l(x1, x1, (r)); x1 ^= x0; }
    TF_R(13) TF_R(15) TF_R(26) TF_R(6)   x0 += k1;  x1 += ks2 + 1u;
    TF_R(17) TF_R(29) TF_R(16) TF_R(24)  x0 += ks2; x1 += k0  + 2u;
    TF_R(13) TF_R(15) TF_R(26) TF_R(6)   x0 += k0;  x1 += k1  + 3u;
    TF_R(17) TF_R(29) TF_R(16) TF_R(24)  x0 += k1;  x1 += ks2 + 4u;
    TF_R(13) TF_R(15) TF_R(26) TF_R(6)   x0 += ks2; x1 += k0  + 5u;
#undef TF_R
    return make_uint2(x0, x1);
}
__device__ __forceinline__ float bits_to_uniform(uint32_t bits) {
    return __uint_as_float((bits >> 9) | 0x3F800000u) - 1.0f;
}

// ---------------- kernel: W1 -> 2-way bf16 split (padded to 448 rows) -----
__global__ void k_split_w1(const float* __restrict__ W1) {
    int gid = blockIdx.x * blockDim.x + threadIdx.x;
    if (gid >= FHP * FIN) return;
    int n = gid / FIN, f = gid - n * FIN;
    float w = (n < FH) ? W1[n * FIN + f] : 0.f;
    __nv_bfloat16 h = __float2bfloat16(w);
    __nv_bfloat16 m = __float2bfloat16(w - __bfloat162float(h));
    g_w1b[gid] = h;
    g_w1b[(size_t)FHP * FIN + gid] = m;
}

// ---------------- kernel: rate encoding -> bf16 spikes ----------------
__global__ void k_gen_spikes(const float* __restrict__ inp) {
    uint32_t q = blockIdx.x * blockDim.x + threadIdx.x;
    if (q >= NTOT / 4) return;
    uint32_t idx0 = q * 4;
    uint32_t b = idx0 / (T_ * FIN);
    uint32_t f = idx0 % FIN;
    float4 p4 = *reinterpret_cast<const float4*>(inp + (size_t)b * FIN + f);
    float pv[4] = {p4.x, p4.y, p4.z, p4.w};
    uint32_t r[4];
#pragma unroll
    for (int j = 0; j < 4; j++) {
        uint2 h = threefry2x32(0u, 42u, 0u, idx0 + j);
        r[j] = (bits_to_uniform(h.y) < pv[j]) ? 0x3F80u : 0u;
    }
    uint2 o;
    o.x = r[0] | (r[1] << 16);
    o.y = r[2] | (r[3] << 16);
    *reinterpret_cast<uint2*>(g_spkb + idx0) = o;
}

// ---------------- GEMM1: a1T[n][m] = spikes[m][k] * (W1hi+W1mid)[n][k] ----
__device__ __forceinline__ void load_stage(uint32_t smb, int s, int kb,
                                           int m_blk, int n_blk, int tid) {
    uint32_t base = smb + s * STAGE_BYTES;
    int k0 = kb * BK;
    // A: 128 rows x 8 x 16B
#pragma unroll
    for (int it = 0; it < 4; it++) {
        int c = tid + it * 256;
        int row = c >> 3, cc = c & 7;
        uint32_t off = sw128(row * 128 + cc * 16);
        cp16(base + off,
             g_spkb + (size_t)(m_blk + row) * FIN + k0 + cc * 8);
    }
    // B: 2 splits x 64 rows x 8 x 16B
#pragma unroll
    for (int it = 0; it < 4; it++) {
        int c = tid + it * 256;
        int sp = c >> 9, row = (c >> 3) & 63, cc = c & 7;
        uint32_t off = sw128(row * 128 + cc * 16);
        cp16(base + STAGE_A + sp * (BN * 128) + off,
             g_w1b + (size_t)sp * FHP * FIN + (size_t)(n_blk + row) * FIN
                   + k0 + cc * 8);
    }
    CP_COMMIT();
}

__global__ __launch_bounds__(256, 2) void k_gemm1() {
    extern __shared__ char sm[];
    uint32_t smb = s2u(sm);
    int tid = threadIdx.x, wid = tid >> 5, lane = tid & 31;
    int m_blk = blockIdx.y * BM;
    int n_blk = blockIdx.x * BN;
    int mw = (wid & 3) * 32;       // warp m offset (4 m-warps x 32)
    int nw = (wid >> 2) * 32;      // warp n offset (2 n-warps x 32)

    float acc[2][4][4];
#pragma unroll
    for (int i = 0; i < 2; i++)
#pragma unroll
        for (int j = 0; j < 4; j++)
#pragma unroll
            for (int r = 0; r < 4; r++) acc[i][j][r] = 0.f;

    load_stage(smb, 0, 0, m_blk, n_blk, tid);
    load_stage(smb, 1, 1, m_blk, n_blk, tid);

    for (int kb = 0; kb < KBLKS; kb++) {
        CP_WAIT(1);
        __syncthreads();
        if (kb + 2 < KBLKS)
            load_stage(smb, (kb + 2) % NSTAGE, kb + 2, m_blk, n_blk, tid);
        else
            CP_COMMIT();

        uint32_t Ab = smb + (kb % NSTAGE) * STAGE_BYTES;
        uint32_t Bb = Ab + STAGE_A;

#pragma unroll
        for (int kk = 0; kk < 4; kk++) {
            uint32_t af[2][4];
#pragma unroll
            for (int i = 0; i < 2; i++) {
                int row = mw + i * 16 + (lane & 15);
                int coff = (kk * 2 + (lane >> 4)) * 16;
                LDSM4(af[i], Ab + sw128(row * 128 + coff));
            }
#pragma unroll
            for (int sp = 0; sp < 2; sp++) {
                uint32_t bf[2][4];
#pragma unroll
                for (int jj = 0; jj < 2; jj++) {
                    int nrow = nw + jj * 16 + ((lane & 16) >> 1) + (lane & 7);
                    int coff = (kk * 2 + ((lane >> 3) & 1)) * 16;
                    LDSM4(bf[jj], Bb + sp * (BN * 128)
                                     + sw128(nrow * 128 + coff));
                }
#pragma unroll
                for (int i = 0; i < 2; i++) {
#pragma unroll
                    for (int j = 0; j < 4; j++) {
                        uint32_t b0 = (j & 1) ? bf[j >> 1][2] : bf[j >> 1][0];
                        uint32_t b1 = (j & 1) ? bf[j >> 1][3] : bf[j >> 1][1];
                        MMA16816(acc[i][j], af[i], b0, b1);
                    }
                }
            }
        }
        // next iteration's barrier protects stage reuse
    }

    // epilogue: write transposed a1T[n][m]   (m always < 9600)
    int g = lane >> 2, t4 = lane & 3;
#pragma unroll
    for (int i = 0; i < 2; i++) {
#pragma unroll
        for (int j = 0; j < 4; j++) {
            int m0 = m_blk + mw + i * 16 + g;
            int n0 = n_blk + nw + j * 8 + t4 * 2;
            if (n0 < FH) {
                g_a1T[(size_t)n0 * MTOT + m0]     = acc[i][j][0];
                g_a1T[(size_t)n0 * MTOT + m0 + 8] = acc[i][j][2];
            }
            if (n0 + 1 < FH) {
                g_a1T[(size_t)(n0+1) * MTOT + m0]     = acc[i][j][1];
                g_a1T[(size_t)(n0+1) * MTOT + m0 + 8] = acc[i][j][3];
            }
        }
    }
}

// ---------------- PSP scan + threshold (layer 1), coalesced via smem ------
// grid = 32 b x 4 o-chunks; block = 128 threads (one per o in chunk).
// t processed in 5 chunks of 60; tile stride 61 floats (odd -> conflict-free).
#define SC_TC 60
__global__ __launch_bounds__(128) void k_scan1() {
    __shared__ float   tile[128 * 61];
    __shared__ uint8_t obuf[128 * SC_TC];
    int b  = blockIdx.x >> 2;
    int o0 = (blockIdx.x & 3) * 128;
    int tid = threadIdx.x;
    float u = 0.f;

    for (int ch = 0; ch < 5; ch++) {
        int t0 = ch * SC_TC;
        // cooperative load: 128 rows x 15 float4 (60 floats)
#pragma unroll
        for (int j = 0; j < 15; j++) {
            int idx = j * 128 + tid;
            int row = idx / 15, c = idx - row * 15;
            int oo = o0 + row;
            float4 v = make_float4(0.f, 0.f, 0.f, 0.f);
            if (oo < FH)
                v = *reinterpret_cast<const float4*>(
                    g_a1T + (size_t)oo * MTOT + b * T_ + t0 + c * 4);
            float* dst = tile + row * 61 + c * 4;
            dst[0] = v.x; dst[1] = v.y; dst[2] = v.z; dst[3] = v.w;
        }
        __syncthreads();
        // per-thread serial scan of 60 steps from smem
        const float* src = tile + tid * 61;
        uint8_t* ob = obuf + tid * SC_TC;
#pragma unroll
        for (int tt = 0; tt < SC_TC; tt++) {
            u = __fadd_rn(__fmul_rn(DECAY, u), src[tt]);
            ob[tt] = (u >= THETA) ? 1 : 0;
        }
        __syncthreads();
        // cooperative store: 128 rows x 15 u32 (60 bytes)
        const uint32_t* ob32 = reinterpret_cast<const uint32_t*>(obuf);
#pragma unroll
        for (int j = 0; j < 15; j++) {
            int idx = j * 128 + tid;
            int row = idx / 15, c = idx - row * 15;
            int oo = o0 + row;
            if (oo < FH)
                *reinterpret_cast<uint32_t*>(
                    g_s1T + ((size_t)b * FH + oo) * T_ + t0 + c * 4)
                    = ob32[row * 15 + c];
        }
        __syncthreads();
    }
}

// ---------------- layer 2 GEMM: grid (b x 5 t-chunks), 60 threads active ---
__global__ __launch_bounds__(64) void k_gemm2(const float* __restrict__ W2) {
    __shared__ float w2t[FH * 12];   // [o][12]: 10 outputs + 2 pad
    int b  = blockIdx.x / 5;
    int tc = blockIdx.x % 5;
    for (int i = threadIdx.x; i < FH * FOUT; i += 64) {
        int o = i / FOUT, ii = i - o * FOUT;
        w2t[o * 12 + ii] = W2[ii * FH + o];
    }
    for (int i = threadIdx.x; i < FH; i += 64) {
        w2t[i * 12 + 10] = 0.f; w2t[i * 12 + 11] = 0.f;
    }
    __syncthreads();
    int t = tc * SC_TC + threadIdx.x;
    if (threadIdx.x >= SC_TC) return;
    const uint8_t* sp = g_s1T + (size_t)b * FH * T_ + t;
    float acc[FOUT];
#pragma unroll
    for (int i = 0; i < FOUT; i++) acc[i] = 0.f;
#pragma unroll 2
    for (int o = 0; o < FH; o++) {
        float s = (float)sp[(size_t)o * T_];
        float4 wa = *reinterpret_cast<const float4*>(w2t + o * 12);
        float4 wb = *reinterpret_cast<const float4*>(w2t + o * 12 + 4);
        float2 wc = *reinterpret_cast<const float2*>(w2t + o * 12 + 8);
        acc[0] = fmaf(s, wa.x, acc[0]); acc[1] = fmaf(s, wa.y, acc[1]);
        acc[2] = fmaf(s, wa.z, acc[2]); acc[3] = fmaf(s, wa.w, acc[3]);
        acc[4] = fmaf(s, wb.x, acc[4]); acc[5] = fmaf(s, wb.y, acc[5]);
        acc[6] = fmaf(s, wb.z, acc[6]); acc[7] = fmaf(s, wb.w, acc[7]);
        acc[8] = fmaf(s, wc.x, acc[8]); acc[9] = fmaf(s, wc.y, acc[9]);
    }
    float* dst = g_a2 + ((size_t)b * T_ + t) * FOUT;
#pragma unroll
    for (int i = 0; i < FOUT; i++) dst[i] = acc[i];
}

// ---------------- layer 2 scan + transpose ----------------
__global__ void k_scan2(float* __restrict__ out) {
    int gid = blockIdx.x * blockDim.x + threadIdx.x;
    if (gid >= B_ * FOUT) return;
    int b = gid / FOUT, o = gid % FOUT;
    const float* p = g_a2 + (size_t)b * T_ * FOUT + o;
    float* q = out + (size_t)b * FOUT * T_ + (size_t)o * T_;
    float u = 0.f, x = p[0];
    for (int t = 0; t < T_; t++) {
        float xn = (t + 1 < T_) ? p[(t + 1) * FOUT] : 0.f;
        u = __fadd_rn(__fmul_rn(DECAY, u), x);
        q[t] = (u >= THETA) ? 1.f : 0.f;
        x = xn;
    }
}

// ---------------- launch ----------------
extern "C" void kernel_launch(void* const* d_in, const int* in_sizes, int n_in,
                              void* d_out, int out_size) {
    const float* inp = (const float*)d_in[0];   // [32,3,32,32]
    const float* W1  = (const float*)d_in[1];   // [410,3072]
    const float* W2  = (const float*)d_in[2];   // [10,410]
    float* out = (float*)d_out;                 // [32,10,300]

    static int smem_set = 0;
    if (!smem_set) {
        cudaFuncSetAttribute(k_gemm1,
            cudaFuncAttributeMaxDynamicSharedMemorySize, GEMM1_SMEM);
        smem_set = 1;
    }

    k_split_w1<<<(FHP * FIN + 255) / 256, 256>>>(W1);
    k_gen_spikes<<<(NTOT / 4 + 255) / 256, 256>>>(inp);

    dim3 g1(FHP / BN, MTOT / BM);               // (7, 75)
    k_gemm1<<<g1, 256, GEMM1_SMEM>>>();

    k_scan1<<<B_ * 4, 128>>>();
    k_gemm2<<<B_ * 5, 64>>>(W2);
    k_scan2<<<(B_ * FOUT + 31) / 32, 32>>>(out);
}